// round 7
// baseline (speedup 1.0000x reference)
#include <cuda_runtime.h>
#include <cstdint>

#define PRIME        2147483647LL
#define N_DIGITS     16
#define N_ARY        32
#define EMB          64
#define NUM_EMB      100000
#define NUM_BUCKETS  65536
#define NUM_HASHES   2
#define BATCH        4096
#define PAIRS        (BATCH * N_DIGITS)

__device__ int   g_bucket[2 * PAIRS];   // 512 KB scratch
__device__ float g_w[2 * PAIRS];        // 512 KB scratch
__device__ int   g_mode;                // 0=int32, 1=int64 LE pairs, 2=float32

struct HashConsts {
    long long seq_a[N_DIGITS];
    long long ha[NUM_HASHES];
    long long hb[NUM_HASHES];
};

// ---------------------------------------------------------------------------
// Host MT19937 == np.random.RandomState(42).randint(low, high) for int64 when
// rng fits in 32 bits: numpy's random_bounded_uint64_fill takes the 32-bit
// branch -> buffered_bounded_masked_uint32: ONE next32() per attempt,
// val = draw & mask, reject while val > rng.
// ---------------------------------------------------------------------------
namespace host_rng {
struct MT19937 {
    uint32_t mt[624];
    int idx;
    void seed(uint32_t s) {
        for (int i = 0; i < 624; i++) {
            mt[i] = s;
            s = 1812433253u * (s ^ (s >> 30)) + (uint32_t)(i + 1);
        }
        idx = 624;
    }
    uint32_t next32() {
        if (idx >= 624) {
            for (int i = 0; i < 624; i++) {
                uint32_t y = (mt[i] & 0x80000000u) | (mt[(i + 1) % 624] & 0x7fffffffu);
                uint32_t v = mt[(i + 397) % 624] ^ (y >> 1);
                if (y & 1u) v ^= 2567483615u;
                mt[i] = v;
            }
            idx = 0;
        }
        uint32_t y = mt[idx++];
        y ^= y >> 11;
        y ^= (y << 7)  & 2636928640u;
        y ^= (y << 15) & 4022730752u;
        y ^= y >> 18;
        return y;
    }
    // numpy randint(low, high) int64, 32-bit masked-rejection branch
    long long randint(long long low, long long high_excl) {
        uint32_t rng = (uint32_t)(high_excl - 1 - low);   // inclusive range
        uint32_t mask = rng;
        mask |= mask >> 1;  mask |= mask >> 2;  mask |= mask >> 4;
        mask |= mask >> 8;  mask |= mask >> 16;
        uint32_t val;
        do { val = next32() & mask; } while (val > rng);
        return low + (long long)val;
    }
};
} // namespace host_rng

static HashConsts make_consts() {
    host_rng::MT19937 rng;
    rng.seed(42u);
    HashConsts c;
    for (int i = 0; i < N_DIGITS; i++)   c.seq_a[i] = rng.randint(1, PRIME);
    for (int i = 0; i < NUM_HASHES; i++) c.ha[i]    = rng.randint(1, PRIME);
    for (int i = 0; i < NUM_HASHES; i++) c.hb[i]    = rng.randint(0, PRIME);
    return c;
}

// ---------------------------------------------------------------------------
// Kernel 0: classify sequence buffer layout from contents.
// ---------------------------------------------------------------------------
__global__ void detect_kernel(const unsigned* __restrict__ seq32) {
    __shared__ unsigned s_odd, s_big;
    if (threadIdx.x == 0) { s_odd = 0u; s_big = 0u; }
    __syncthreads();
    unsigned odd = 0u, big = 0u;
    for (int i = threadIdx.x; i < PAIRS; i += blockDim.x) {
        unsigned v = seq32[i];
        if ((i & 1) && v != 0u) odd = 1u;
        if (v >= 0x3F000000u)   big = 1u;
    }
    if (odd) atomicOr(&s_odd, 1u);
    if (big) atomicOr(&s_big, 1u);
    __syncthreads();
    if (threadIdx.x == 0)
        g_mode = s_big ? 2 : (s_odd ? 0 : 1);
}

// ---------------------------------------------------------------------------
// Kernel 1: prefix hashes -> bucket ids + importance weights (d-major scratch)
// ---------------------------------------------------------------------------
__global__ void hash_kernel(const void* __restrict__ seq_raw,
                            const float* __restrict__ iw,
                            HashConsts c) {
    int b = blockIdx.x * blockDim.x + threadIdx.x;
    if (b >= BATCH) return;

    const int*   s32 = (const int*)seq_raw;
    const float* f32 = (const float*)seq_raw;
    int mode = g_mode;

    long long hs[N_DIGITS];
    long long h = 0;
    int len = 0;
#pragma unroll
    for (int d = 0; d < N_DIGITS; d++) {
        int idx = b * N_DIGITS + d;
        long long v;
        if (mode == 0)      v = (long long)s32[idx];
        else if (mode == 1) v = (long long)s32[2 * idx];
        else                v = (long long)f32[idx];
        if (v != 0) len++;
        h = (h + c.seq_a[d] * v) % PRIME;   // v in [0,32): no pre-mod needed
        hs[d] = h;
    }
    int last = (len - 1 > 0) ? (len - 1) : 0;

#pragma unroll
    for (int d = 0; d < N_DIGITS; d++) {
        long long id = hs[d < last ? d : last];
        int s = d * BATCH + b;
        int iwrow = (int)(id % NUM_EMB);
        g_w[2 * s + 0] = iw[(size_t)iwrow * NUM_HASHES + 0];
        g_w[2 * s + 1] = iw[(size_t)iwrow * NUM_HASHES + 1];
        g_bucket[2 * s + 0] = (int)(((c.ha[0] * id + c.hb[0]) % PRIME) % NUM_BUCKETS);
        g_bucket[2 * s + 1] = (int)(((c.ha[1] * id + c.hb[1]) % PRIME) % NUM_BUCKETS);
    }
}

// ---------------------------------------------------------------------------
// Kernel 2: out[b,d,a] = sum_e (w0*T[bkt0][a*64+e] + w1*T[bkt1][a*64+e]) * rep[b,d,e]
// Block = one (b,d) pair, blockIdx.x = d*BATCH + b (d-major for L2 reuse).
// 128 threads; each half-warp computes one 'a' per iteration via coalesced
// float4 loads of both bucket rows (8 independent LDG.128 in flight / block).
// ---------------------------------------------------------------------------
__global__ void __launch_bounds__(128, 8)
logits_kernel(const float* __restrict__ rep,
              const float* __restrict__ table,
              float* __restrict__ out) {
    int p = blockIdx.x;            // d*BATCH + b
    int d = p >> 12;
    int b = p & (BATCH - 1);
    int tid  = threadIdx.x;
    int warp = tid >> 5;
    int lane = tid & 31;
    int half = lane >> 4;
    int hl   = lane & 15;

    float w0 = g_w[2 * p + 0];
    float w1 = g_w[2 * p + 1];
    const float4* r0 = (const float4*)(table + (size_t)g_bucket[2 * p + 0] * (N_ARY * EMB));
    const float4* r1 = (const float4*)(table + (size_t)g_bucket[2 * p + 1] * (N_ARY * EMB));

    size_t bd = (size_t)b * N_DIGITS + d;
    const float4* rp = (const float4*)(rep + bd * EMB);
    float4 r = rp[hl];

    float* o = out + bd * N_ARY;

#pragma unroll
    for (int i = 0; i < 4; i++) {
        int a   = warp * 8 + 2 * i + half;
        int idx = a * 16 + hl;
        float4 c0 = __ldg(&r0[idx]);
        float4 c1 = __ldg(&r1[idx]);
        float cx = w0 * c0.x + w1 * c1.x;
        float cy = w0 * c0.y + w1 * c1.y;
        float cz = w0 * c0.z + w1 * c1.z;
        float cw = w0 * c0.w + w1 * c1.w;
        float partial = cx * r.x + cy * r.y + cz * r.z + cw * r.w;
#pragma unroll
        for (int off = 8; off > 0; off >>= 1)
            partial += __shfl_xor_sync(0xffffffffu, partial, off);
        if (hl == 0)
            o[a] = partial;
    }
}

// ---------------------------------------------------------------------------
// Launch. Inputs identified BY SIZE (robust to ordering):
//   seq: smallest, table: largest, iw: 200000, rep: 4194304.
// ---------------------------------------------------------------------------
extern "C" void kernel_launch(void* const* d_in, const int* in_sizes, int n_in,
                              void* d_out, int out_size) {
    (void)out_size;
    const void*  seq   = nullptr;
    const float* rep   = nullptr;
    const float* iw    = nullptr;
    const float* table = nullptr;

    long long best_small = 0x7fffffffffffffffLL, best_big = -1;
    int small_i = 0, big_i = 0;
    for (int i = 0; i < n_in; i++) {
        long long sz = in_sizes[i];
        if (sz < best_small) { best_small = sz; seq = d_in[i]; small_i = i; }
        if (sz > best_big)   { best_big = sz; table = (const float*)d_in[i]; big_i = i; }
    }
    for (int i = 0; i < n_in; i++) {
        if (i == small_i || i == big_i) continue;
        if ((long long)in_sizes[i] < 1000000) iw = (const float*)d_in[i];
        else                                  rep = (const float*)d_in[i];
    }

    HashConsts c = make_consts();   // host-only; baked into graph node params

    detect_kernel<<<1, 256>>>((const unsigned*)seq);
    hash_kernel<<<(BATCH + 255) / 256, 256>>>(seq, iw, c);
    logits_kernel<<<PAIRS, 128>>>(rep, table, (float*)d_out);
}

// round 11
// speedup vs baseline: 1.0999x; 1.0999x over previous
#include <cuda_runtime.h>
#include <cstdint>

#define PRIME        2147483647LL
#define N_DIGITS     16
#define N_ARY        32
#define EMB          64
#define NUM_EMB      100000
#define NUM_BUCKETS  65536
#define NUM_HASHES   2
#define BATCH        4096
#define PAIRS        (BATCH * N_DIGITS)

struct __align__(16) PairRec {
    float w0, w1;
    int   b0, b1;
};
__device__ PairRec  g_rec[PAIRS];       // 1 MB scratch
__device__ unsigned g_flags;            // detection flag bits
__device__ int      g_mode;             // 0=int32, 1=int64 LE pairs, 2=float32

struct HashConsts {
    long long seq_a[N_DIGITS];
    long long ha[NUM_HASHES];
    long long hb[NUM_HASHES];
};

// ---------------------------------------------------------------------------
// Host MT19937 == np.random.RandomState(42).randint, int64 dtype, range < 2^32:
// numpy's 32-bit masked-rejection branch (one next32() per attempt).
// ---------------------------------------------------------------------------
namespace host_rng {
struct MT19937 {
    uint32_t mt[624];
    int idx;
    void seed(uint32_t s) {
        for (int i = 0; i < 624; i++) {
            mt[i] = s;
            s = 1812433253u * (s ^ (s >> 30)) + (uint32_t)(i + 1);
        }
        idx = 624;
    }
    uint32_t next32() {
        if (idx >= 624) {
            for (int i = 0; i < 624; i++) {
                uint32_t y = (mt[i] & 0x80000000u) | (mt[(i + 1) % 624] & 0x7fffffffu);
                uint32_t v = mt[(i + 397) % 624] ^ (y >> 1);
                if (y & 1u) v ^= 2567483615u;
                mt[i] = v;
            }
            idx = 0;
        }
        uint32_t y = mt[idx++];
        y ^= y >> 11;
        y ^= (y << 7)  & 2636928640u;
        y ^= (y << 15) & 4022730752u;
        y ^= y >> 18;
        return y;
    }
    long long randint(long long low, long long high_excl) {
        uint32_t rng = (uint32_t)(high_excl - 1 - low);
        uint32_t mask = rng;
        mask |= mask >> 1;  mask |= mask >> 2;  mask |= mask >> 4;
        mask |= mask >> 8;  mask |= mask >> 16;
        uint32_t val;
        do { val = next32() & mask; } while (val > rng);
        return low + (long long)val;
    }
};
} // namespace host_rng

static HashConsts make_consts() {
    host_rng::MT19937 rng;
    rng.seed(42u);
    HashConsts c;
    for (int i = 0; i < N_DIGITS; i++)   c.seq_a[i] = rng.randint(1, PRIME);
    for (int i = 0; i < NUM_HASHES; i++) c.ha[i]    = rng.randint(1, PRIME);
    for (int i = 0; i < NUM_HASHES; i++) c.hb[i]    = rng.randint(0, PRIME);
    return c;
}

// ---------------------------------------------------------------------------
// Detection: sample first 8192 words in parallel (~1-2 us total).
// ---------------------------------------------------------------------------
#define DETECT_WORDS 8192

__global__ void detect_reset() { g_flags = 0u; }

__global__ void detect_kernel(const unsigned* __restrict__ seq32) {
    int i = blockIdx.x * blockDim.x + threadIdx.x;
    unsigned v = seq32[i];
    unsigned odd = ((i & 1) && v != 0u) ? 1u : 0u;
    unsigned big = (v >= 0x3F000000u) ? 1u : 0u;
    unsigned f = (__ballot_sync(0xffffffffu, odd) ? 1u : 0u)
               | (__ballot_sync(0xffffffffu, big) ? 2u : 0u);
    if ((threadIdx.x & 31) == 0 && f)
        atomicOr(&g_flags, f);
}

__global__ void detect_finalize() {
    unsigned f = g_flags;
    g_mode = (f & 2u) ? 2 : ((f & 1u) ? 0 : 1);
}

// ---------------------------------------------------------------------------
// Kernel 1: prefix hashes -> packed per-pair records (d-major: s = d*BATCH+b)
// ---------------------------------------------------------------------------
__global__ void hash_kernel(const void* __restrict__ seq_raw,
                            const float* __restrict__ iw,
                            HashConsts c) {
    int b = blockIdx.x * blockDim.x + threadIdx.x;
    if (b >= BATCH) return;

    const int*   s32 = (const int*)seq_raw;
    const float* f32 = (const float*)seq_raw;
    int mode = g_mode;

    long long hs[N_DIGITS];
    long long h = 0;
    int len = 0;
#pragma unroll
    for (int d = 0; d < N_DIGITS; d++) {
        int idx = b * N_DIGITS + d;
        long long v;
        if (mode == 0)      v = (long long)s32[idx];
        else if (mode == 1) v = (long long)s32[2 * idx];
        else                v = (long long)f32[idx];
        if (v != 0) len++;
        h = (h + c.seq_a[d] * v) % PRIME;   // v in [0,32): no pre-mod needed
        hs[d] = h;
    }
    int last = (len - 1 > 0) ? (len - 1) : 0;

#pragma unroll
    for (int d = 0; d < N_DIGITS; d++) {
        long long id = hs[d < last ? d : last];
        int iwrow = (int)(id % NUM_EMB);
        PairRec r;
        r.w0 = iw[(size_t)iwrow * NUM_HASHES + 0];
        r.w1 = iw[(size_t)iwrow * NUM_HASHES + 1];
        r.b0 = (int)(((c.ha[0] * id + c.hb[0]) % PRIME) % NUM_BUCKETS);
        r.b1 = (int)(((c.ha[1] * id + c.hb[1]) % PRIME) % NUM_BUCKETS);
        g_rec[d * BATCH + b] = r;
    }
}

// ---------------------------------------------------------------------------
// Kernel 2: out[b,d,a] = sum_e (w0*T[b0][a*64+e] + w1*T[b1][a*64+e]) * rep[b,d,e]
// Block = one (b,d) pair, d-major. 128 threads; half-warp per 'a' per iter.
// ---------------------------------------------------------------------------
__global__ void __launch_bounds__(128, 8)
logits_kernel(const float* __restrict__ rep,
              const float* __restrict__ table,
              float* __restrict__ out) {
    int p = blockIdx.x;            // d*BATCH + b
    int d = p >> 12;
    int b = p & (BATCH - 1);
    int tid  = threadIdx.x;
    int warp = tid >> 5;
    int lane = tid & 31;
    int half = lane >> 4;
    int hl   = lane & 15;

    PairRec rec = g_rec[p];        // single LDG.128
    float w0 = rec.w0, w1 = rec.w1;
    const float4* r0 = (const float4*)(table + (size_t)rec.b0 * (N_ARY * EMB));
    const float4* r1 = (const float4*)(table + (size_t)rec.b1 * (N_ARY * EMB));

    size_t bd = (size_t)b * N_DIGITS + d;
    const float4* rp = (const float4*)(rep + bd * EMB);
    float4 r = rp[hl];

    float* o = out + bd * N_ARY;

#pragma unroll
    for (int i = 0; i < 4; i++) {
        int a   = warp * 8 + 2 * i + half;
        int idx = a * 16 + hl;
        float4 c0 = __ldg(&r0[idx]);
        float4 c1 = __ldg(&r1[idx]);
        float cx = w0 * c0.x + w1 * c1.x;
        float cy = w0 * c0.y + w1 * c1.y;
        float cz = w0 * c0.z + w1 * c1.z;
        float cw = w0 * c0.w + w1 * c1.w;
        float partial = cx * r.x + cy * r.y + cz * r.z + cw * r.w;
#pragma unroll
        for (int off = 8; off > 0; off >>= 1)
            partial += __shfl_xor_sync(0xffffffffu, partial, off);
        if (hl == 0)
            o[a] = partial;
    }
}

extern "C" void kernel_launch(void* const* d_in, const int* in_sizes, int n_in,
                              void* d_out, int out_size) {
    (void)out_size;
    const void*  seq   = nullptr;
    const float* rep   = nullptr;
    const float* iw    = nullptr;
    const float* table = nullptr;

    long long best_small = 0x7fffffffffffffffLL, best_big = -1;
    int small_i = 0, big_i = 0;
    for (int i = 0; i < n_in; i++) {
        long long sz = in_sizes[i];
        if (sz < best_small) { best_small = sz; seq = d_in[i]; small_i = i; }
        if (sz > best_big)   { best_big = sz; table = (const float*)d_in[i]; big_i = i; }
    }
    for (int i = 0; i < n_in; i++) {
        if (i == small_i || i == big_i) continue;
        if ((long long)in_sizes[i] < 1000000) iw = (const float*)d_in[i];
        else                                  rep = (const float*)d_in[i];
    }

    HashConsts c = make_consts();   // host-only; baked into graph node params

    detect_reset<<<1, 1>>>();
    detect_kernel<<<DETECT_WORDS / 256, 256>>>((const unsigned*)seq);
    detect_finalize<<<1, 1>>>();
    hash_kernel<<<(BATCH + 255) / 256, 256>>>(seq, iw, c);
    logits_kernel<<<PAIRS, 128>>>(rep, table, (float*)d_out);
}

// round 13
// speedup vs baseline: 1.1496x; 1.0451x over previous
#include <cuda_runtime.h>
#include <cstdint>

#define PRIME        2147483647LL
#define PRIME_U      2147483647ULL
#define N_DIGITS     16
#define N_ARY        32
#define EMB          64
#define NUM_EMB      100000
#define NUM_BUCKETS  65536
#define NUM_HASHES   2
#define BATCH        4096
#define PAIRS        (BATCH * N_DIGITS)

struct __align__(16) PairRec {
    float w0, w1;
    int   b0, b1;
};
__device__ PairRec g_rec[PAIRS];   // 1 MB scratch
__device__ int     g_mode;         // 0=int32, 1=int64 LE pairs, 2=float32

struct HashConsts {
    long long seq_a[N_DIGITS];
    long long ha[NUM_HASHES];
    long long hb[NUM_HASHES];
};

// ---------------------------------------------------------------------------
// Host MT19937 == np.random.RandomState(42).randint, int64 dtype, range < 2^32:
// numpy's 32-bit masked-rejection branch (one next32() per attempt).
// ---------------------------------------------------------------------------
namespace host_rng {
struct MT19937 {
    uint32_t mt[624];
    int idx;
    void seed(uint32_t s) {
        for (int i = 0; i < 624; i++) {
            mt[i] = s;
            s = 1812433253u * (s ^ (s >> 30)) + (uint32_t)(i + 1);
        }
        idx = 624;
    }
    uint32_t next32() {
        if (idx >= 624) {
            for (int i = 0; i < 624; i++) {
                uint32_t y = (mt[i] & 0x80000000u) | (mt[(i + 1) % 624] & 0x7fffffffu);
                uint32_t v = mt[(i + 397) % 624] ^ (y >> 1);
                if (y & 1u) v ^= 2567483615u;
                mt[i] = v;
            }
            idx = 0;
        }
        uint32_t y = mt[idx++];
        y ^= y >> 11;
        y ^= (y << 7)  & 2636928640u;
        y ^= (y << 15) & 4022730752u;
        y ^= y >> 18;
        return y;
    }
    long long randint(long long low, long long high_excl) {
        uint32_t rng = (uint32_t)(high_excl - 1 - low);
        uint32_t mask = rng;
        mask |= mask >> 1;  mask |= mask >> 2;  mask |= mask >> 4;
        mask |= mask >> 8;  mask |= mask >> 16;
        uint32_t val;
        do { val = next32() & mask; } while (val > rng);
        return low + (long long)val;
    }
};
} // namespace host_rng

static HashConsts make_consts() {
    host_rng::MT19937 rng;
    rng.seed(42u);
    HashConsts c;
    for (int i = 0; i < N_DIGITS; i++)   c.seq_a[i] = rng.randint(1, PRIME);
    for (int i = 0; i < NUM_HASHES; i++) c.ha[i]    = rng.randint(1, PRIME);
    for (int i = 0; i < NUM_HASHES; i++) c.hb[i]    = rng.randint(0, PRIME);
    return c;
}

// ---------------------------------------------------------------------------
// Mersenne reduction: x mod (2^31 - 1) for x < 2^63.
// Two folds bring x below 2^32; final conditional subtracts.
// ---------------------------------------------------------------------------
__device__ __forceinline__ unsigned long long mod31(unsigned long long x) {
    x = (x >> 31) + (x & PRIME_U);   // < 2^32 + 2^31
    x = (x >> 31) + (x & PRIME_U);   // < PRIME + 3
    if (x >= PRIME_U) x -= PRIME_U;
    if (x >= PRIME_U) x -= PRIME_U;
    return x;
}

// ---------------------------------------------------------------------------
// Detection (single launch): one block of 1024 threads scans the first 8192
// words. int64 LE pairs -> all odd words zero; float32 -> words >= 0x3F000000.
// ---------------------------------------------------------------------------
#define DETECT_WORDS 8192
__global__ void detect_kernel(const unsigned* __restrict__ seq32) {
    __shared__ unsigned s_odd, s_big;
    if (threadIdx.x == 0) { s_odd = 0u; s_big = 0u; }
    __syncthreads();
    unsigned odd = 0u, big = 0u;
#pragma unroll
    for (int k = 0; k < DETECT_WORDS / 1024; k++) {
        int i = k * 1024 + threadIdx.x;
        unsigned v = seq32[i];
        if ((i & 1) && v != 0u) odd = 1u;
        if (v >= 0x3F000000u)   big = 1u;
    }
    if (__ballot_sync(0xffffffffu, odd) && (threadIdx.x & 31) == 0) atomicOr(&s_odd, 1u);
    if (__ballot_sync(0xffffffffu, big) && (threadIdx.x & 31) == 0) atomicOr(&s_big, 1u);
    __syncthreads();
    if (threadIdx.x == 0)
        g_mode = s_big ? 2 : (s_odd ? 0 : 1);
}

// ---------------------------------------------------------------------------
// Kernel 1: prefix hashes -> packed per-pair records (d-major: s = d*BATCH+b).
// Raw cumsum (terms < 2^36, total < 2^40) with NO mod on the dependency chain;
// Mersenne folds applied off-chain per digit.
// ---------------------------------------------------------------------------
__global__ void hash_kernel(const void* __restrict__ seq_raw,
                            const float* __restrict__ iw,
                            HashConsts c) {
    int b = blockIdx.x * blockDim.x + threadIdx.x;
    if (b >= BATCH) return;

    const int*   s32 = (const int*)seq_raw;
    const float* f32 = (const float*)seq_raw;
    int mode = g_mode;

    unsigned long long raw[N_DIGITS];
    unsigned long long acc = 0;
    int len = 0;
#pragma unroll
    for (int d = 0; d < N_DIGITS; d++) {
        int idx = b * N_DIGITS + d;
        long long v;
        if (mode == 0)      v = (long long)s32[idx];
        else if (mode == 1) v = (long long)s32[2 * idx];
        else                v = (long long)f32[idx];
        if (v != 0) len++;
        acc += (unsigned long long)c.seq_a[d] * (unsigned long long)v;  // < 2^40 total
        raw[d] = acc;
    }
    int last = (len - 1 > 0) ? (len - 1) : 0;

#pragma unroll
    for (int d = 0; d < N_DIGITS; d++) {
        unsigned long long id = mod31(raw[d < last ? d : last]);
        int iwrow = (int)(id % NUM_EMB);
        PairRec r;
        r.w0 = iw[(size_t)iwrow * NUM_HASHES + 0];
        r.w1 = iw[(size_t)iwrow * NUM_HASHES + 1];
        r.b0 = (int)(mod31((unsigned long long)c.ha[0] * id + (unsigned long long)c.hb[0]) & (NUM_BUCKETS - 1));
        r.b1 = (int)(mod31((unsigned long long)c.ha[1] * id + (unsigned long long)c.hb[1]) & (NUM_BUCKETS - 1));
        g_rec[d * BATCH + b] = r;
    }
}

// ---------------------------------------------------------------------------
// Kernel 2: out[b,d,a] = sum_e (w0*T[b0][a*64+e] + w1*T[b1][a*64+e]) * rep[b,d,e]
// Block = one (b,d) pair, blockIdx.x = d*BATCH + b (d-major for L2 reuse).
// 128 threads; each half-warp computes one 'a' per iteration via coalesced
// float4 loads of both bucket rows.
// ---------------------------------------------------------------------------
__global__ void __launch_bounds__(128, 8)
logits_kernel(const float* __restrict__ rep,
              const float* __restrict__ table,
              float* __restrict__ out) {
    int p = blockIdx.x;            // d*BATCH + b
    int d = p >> 12;
    int b = p & (BATCH - 1);
    int tid  = threadIdx.x;
    int warp = tid >> 5;
    int lane = tid & 31;
    int half = lane >> 4;
    int hl   = lane & 15;

    PairRec rec = g_rec[p];        // single LDG.128
    float w0 = rec.w0, w1 = rec.w1;
    const float4* r0 = (const float4*)(table + (size_t)rec.b0 * (N_ARY * EMB));
    const float4* r1 = (const float4*)(table + (size_t)rec.b1 * (N_ARY * EMB));

    size_t bd = (size_t)b * N_DIGITS + d;
    const float4* rp = (const float4*)(rep + bd * EMB);
    float4 r = rp[hl];

    float* o = out + bd * N_ARY;

#pragma unroll
    for (int i = 0; i < 4; i++) {
        int a   = warp * 8 + 2 * i + half;
        int idx = a * 16 + hl;
        float4 c0 = __ldg(&r0[idx]);
        float4 c1 = __ldg(&r1[idx]);
        float cx = w0 * c0.x + w1 * c1.x;
        float cy = w0 * c0.y + w1 * c1.y;
        float cz = w0 * c0.z + w1 * c1.z;
        float cw = w0 * c0.w + w1 * c1.w;
        float partial = cx * r.x + cy * r.y + cz * r.z + cw * r.w;
#pragma unroll
        for (int off = 8; off > 0; off >>= 1)
            partial += __shfl_xor_sync(0xffffffffu, partial, off);
        if (hl == 0)
            o[a] = partial;
    }
}

// ---------------------------------------------------------------------------
// Launch. Inputs identified BY SIZE (robust to ordering):
//   seq: smallest, table: largest, iw: 200000, rep: 4194304.
// ---------------------------------------------------------------------------
extern "C" void kernel_launch(void* const* d_in, const int* in_sizes, int n_in,
                              void* d_out, int out_size) {
    (void)out_size;
    const void*  seq   = nullptr;
    const float* rep   = nullptr;
    const float* iw    = nullptr;
    const float* table = nullptr;

    long long best_small = 0x7fffffffffffffffLL, best_big = -1;
    int small_i = 0, big_i = 0;
    for (int i = 0; i < n_in; i++) {
        long long sz = in_sizes[i];
        if (sz < best_small) { best_small = sz; seq = d_in[i]; small_i = i; }
        if (sz > best_big)   { best_big = sz; table = (const float*)d_in[i]; big_i = i; }
    }
    for (int i = 0; i < n_in; i++) {
        if (i == small_i || i == big_i) continue;
        if ((long long)in_sizes[i] < 1000000) iw = (const float*)d_in[i];
        else                                  rep = (const float*)d_in[i];
    }

    HashConsts c = make_consts();   // host-only; baked into graph node params

    detect_kernel<<<1, 1024>>>((const unsigned*)seq);
    hash_kernel<<<(BATCH + 127) / 128, 128>>>(seq, iw, c);
    logits_kernel<<<PAIRS, 128>>>(rep, table, (float*)d_out);
}